// round 11
// baseline (speedup 1.0000x reference)
#include <cuda_runtime.h>
#include <cuda_fp16.h>
#include <cstdint>

#define NMAX 50000
#define EMAX 800000

// Scratch (device globals -- no allocation allowed in kernel_launch)
__device__ float  g_agg[NMAX * 64];
__device__ __half g_x16[NMAX * 64];
__device__ __half g_h16A[NMAX * 64];
__device__ __half g_h16B[NMAX * 64];
__device__ int    g_deg[NMAX];
__device__ int    g_off[NMAX + 1];
__device__ int    g_cur[NMAX];
__device__ int    g_csr[EMAX];
__device__ int    g_bsum[128];

// ---------------- fp32 -> fp16 conversion (+ fused deg zeroing) ----------------

__global__ void k_tofp16_zero(const float* __restrict__ src, __half* __restrict__ dst,
                              int n8, int n) {
    int i = blockIdx.x * blockDim.x + threadIdx.x;
    if (i < n) g_deg[i] = 0;
    if (i >= n8) return;
    float4 a = ((const float4*)src)[i * 2];
    float4 b = ((const float4*)src)[i * 2 + 1];
    __half2 h0 = __floats2half2_rn(a.x, a.y);
    __half2 h1 = __floats2half2_rn(a.z, a.w);
    __half2 h2 = __floats2half2_rn(b.x, b.y);
    __half2 h3 = __floats2half2_rn(b.z, b.w);
    uint4 o;
    o.x = reinterpret_cast<unsigned&>(h0);
    o.y = reinterpret_cast<unsigned&>(h1);
    o.z = reinterpret_cast<unsigned&>(h2);
    o.w = reinterpret_cast<unsigned&>(h3);
    ((uint4*)dst)[i] = o;
}

// ---------------- CSR build ----------------

__global__ void k_count(const int* __restrict__ ei, int e) {
    int i4 = (blockIdx.x * blockDim.x + threadIdx.x) * 4;
    if (i4 >= e) return;
    int cnt = e - i4; if (cnt > 4) cnt = 4;
    int d[4];
    #pragma unroll
    for (int u = 0; u < 4; u++) if (u < cnt) d[u] = __ldg(ei + e + i4 + u);
    #pragma unroll
    for (int u = 0; u < 4; u++) if (u < cnt) atomicAdd(&g_deg[d[u]], 1);
}

__global__ void k_blocksum(int n) {
    __shared__ int sm[256];
    int t = threadIdx.x, b = blockIdx.x;
    int base = b * 1024 + t * 4;
    int s = 0;
    #pragma unroll
    for (int u = 0; u < 4; u++) { int i = base + u; if (i < n) s += g_deg[i]; }
    sm[t] = s; __syncthreads();
    #pragma unroll
    for (int o = 128; o; o >>= 1) { if (t < o) sm[t] += sm[t + o]; __syncthreads(); }
    if (t == 0) g_bsum[b] = sm[0];
}

__global__ void k_offsets(int n, int e) {
    __shared__ int sm[256];
    int t = threadIdx.x, b = blockIdx.x;

    int v0 = (t < b) ? g_bsum[t] : 0;
    sm[t] = v0; __syncthreads();
    #pragma unroll
    for (int o = 128; o; o >>= 1) { if (t < o) sm[t] += sm[t + o]; __syncthreads(); }
    int bpre = sm[0];
    __syncthreads();

    int base = b * 1024 + t * 4;
    int vv[4]; int s = 0;
    #pragma unroll
    for (int u = 0; u < 4; u++) { vv[u] = (base + u < n) ? g_deg[base + u] : 0; s += vv[u]; }
    sm[t] = s; __syncthreads();
    #pragma unroll
    for (int o = 1; o < 256; o <<= 1) {
        int val = (t >= o) ? sm[t - o] : 0;
        __syncthreads();
        sm[t] += val;
        __syncthreads();
    }
    int excl = sm[t] - s + bpre;
    #pragma unroll
    for (int u = 0; u < 4; u++) {
        if (base + u < n) { g_off[base + u] = excl; g_cur[base + u] = excl; excl += vv[u]; }
    }
    if (b == 0 && t == 0) g_off[n] = e;
}

__global__ void k_place(const int* __restrict__ ei, int e) {
    int i4 = (blockIdx.x * blockDim.x + threadIdx.x) * 4;
    if (i4 >= e) return;
    int cnt = e - i4; if (cnt > 4) cnt = 4;
    int s[4], d[4], p[4];
    #pragma unroll
    for (int u = 0; u < 4; u++) if (u < cnt) {
        s[u] = __ldg(ei + i4 + u);
        d[u] = __ldg(ei + e + i4 + u);
    }
    #pragma unroll
    for (int u = 0; u < 4; u++) if (u < cnt) p[u] = atomicAdd(&g_cur[d[u]], 1);
    #pragma unroll
    for (int u = 0; u < 4; u++) if (u < cnt) g_csr[p[u]] = s[u];
}

// ---------------- mean aggregation: 8 lanes/node, fp16 gather, fp32 accumulate ----------------

__device__ __forceinline__ void addh(float2 acc[4], uint4 v) {
    float2 f;
    f = __half22float2(reinterpret_cast<__half2&>(v.x)); acc[0].x += f.x; acc[0].y += f.y;
    f = __half22float2(reinterpret_cast<__half2&>(v.y)); acc[1].x += f.x; acc[1].y += f.y;
    f = __half22float2(reinterpret_cast<__half2&>(v.z)); acc[2].x += f.x; acc[2].y += f.y;
    f = __half22float2(reinterpret_cast<__half2&>(v.w)); acc[3].x += f.x; acc[3].y += f.y;
}

__global__ void k_aggregate(const __half* __restrict__ h16, int n) {
    int t = blockIdx.x * blockDim.x + threadIdx.x;
    int node = t >> 3;
    int lane = t & 7;
    if (node >= n) return;
    int beg = g_off[node];
    int end = g_off[node + 1];

    float2 acc[4];
    acc[0] = acc[1] = acc[2] = acc[3] = make_float2(0.f, 0.f);

    int j = beg;
    for (; j + 3 < end; j += 4) {
        int s0 = __ldg(g_csr + j),     s1 = __ldg(g_csr + j + 1);
        int s2 = __ldg(g_csr + j + 2), s3 = __ldg(g_csr + j + 3);
        uint4 v0 = *(const uint4*)(h16 + (size_t)s0 * 64 + lane * 8);
        uint4 v1 = *(const uint4*)(h16 + (size_t)s1 * 64 + lane * 8);
        uint4 v2 = *(const uint4*)(h16 + (size_t)s2 * 64 + lane * 8);
        uint4 v3 = *(const uint4*)(h16 + (size_t)s3 * 64 + lane * 8);
        addh(acc, v0); addh(acc, v1); addh(acc, v2); addh(acc, v3);
    }
    for (; j < end; j++) {
        int s = __ldg(g_csr + j);
        uint4 v = *(const uint4*)(h16 + (size_t)s * 64 + lane * 8);
        addh(acc, v);
    }
    float inv = 1.0f / fmaxf((float)(end - beg), 1.0f);
    float4 o0 = make_float4(acc[0].x * inv, acc[0].y * inv, acc[1].x * inv, acc[1].y * inv);
    float4 o1 = make_float4(acc[2].x * inv, acc[2].y * inv, acc[3].x * inv, acc[3].y * inv);
    *(float4*)(g_agg + (size_t)node * 64 + lane * 8)     = o0;
    *(float4*)(g_agg + (size_t)node * 64 + lane * 8 + 4) = o1;
}

// ---------------- mma.sync SAGE transform ----------------
// Per block: 128 rows x 64 cols, K = 128.
// A = [fp16(mean_nb) | root16]: 128 rows x 136 halves (padded, ldmatrix
// conflict-free: 272B row step = 4-bank shift). Bt = W^T: 64 x 136 halves.
// 4 warps x (32 rows x 64 cols) via m16n8k16 HMMA, fp32 accum.

#define APAD_H 136                       // halves per padded row
#define AROW_B (APAD_H * 2)              // 272 bytes
#define SM_A   0
#define SM_BT  (128 * AROW_B)            // 34816
#define SM_BIAS (SM_BT + 64 * AROW_B)    // 52224
#define SM_WO  (SM_BIAS + 256)           // 52480
#define SM_TOT (SM_WO + 256)             // 52736

__device__ __forceinline__ uint32_t smem_u32(const void* p) {
    uint32_t a;
    asm("{ .reg .u64 t; cvta.to.shared.u64 t, %1; cvt.u32.u64 %0, t; }"
        : "=r"(a) : "l"(p));
    return a;
}

__device__ __forceinline__ void ldsm_x4(uint32_t& r0, uint32_t& r1,
                                        uint32_t& r2, uint32_t& r3, uint32_t addr) {
    asm volatile("ldmatrix.sync.aligned.m8n8.x4.shared.b16 {%0,%1,%2,%3}, [%4];"
                 : "=r"(r0), "=r"(r1), "=r"(r2), "=r"(r3) : "r"(addr));
}

__device__ __forceinline__ void mma16816(float c[4], uint32_t a0, uint32_t a1,
                                         uint32_t a2, uint32_t a3,
                                         uint32_t b0, uint32_t b1) {
    asm volatile(
        "mma.sync.aligned.m16n8k16.row.col.f32.f16.f16.f32 "
        "{%0,%1,%2,%3}, {%4,%5,%6,%7}, {%8,%9}, {%0,%1,%2,%3};"
        : "+f"(c[0]), "+f"(c[1]), "+f"(c[2]), "+f"(c[3])
        : "r"(a0), "r"(a1), "r"(a2), "r"(a3), "r"(b0), "r"(b1));
}

__global__ void __launch_bounds__(128) k_transform_mma(
    const __half* __restrict__ root16,
    const float* __restrict__ Wl, const float* __restrict__ bl,
    const float* __restrict__ Wr,
    __half* __restrict__ out16,
    const float* __restrict__ Wo, const float* __restrict__ bo,
    float* __restrict__ outv,
    int n, int do_head)
{
    extern __shared__ __align__(16) char smem[];
    __half* As  = (__half*)(smem + SM_A);
    __half* Bt  = (__half*)(smem + SM_BT);
    float* bias = (float*)(smem + SM_BIAS);
    float* wos  = (float*)(smem + SM_WO);
    const int tid = threadIdx.x;
    const int wid = tid >> 5;
    const int lane = tid & 31;
    const int row0 = blockIdx.x * 128;

    if (tid < 16) ((float4*)bias)[tid] = ((const float4*)bl)[tid];
    else if (tid < 32) {
        if (do_head) ((float4*)wos)[tid - 16] = ((const float4*)Wo)[tid - 16];
        else         ((float4*)wos)[tid - 16] = make_float4(0.f, 0.f, 0.f, 0.f);
    }

    // ---- stage A: rows = nodes, cols 0..63 = fp16(agg), 64..127 = root16 ----
    for (int idx = tid; idx < 2048; idx += 128) {
        int r = idx >> 4;       // 0..127
        int g = idx & 15;       // 8-half group
        int gr = row0 + r;
        uint4 val = make_uint4(0u, 0u, 0u, 0u);
        if (gr < n) {
            if (g < 8) {
                float4 a0 = *(const float4*)(g_agg + (size_t)gr * 64 + g * 8);
                float4 a1 = *(const float4*)(g_agg + (size_t)gr * 64 + g * 8 + 4);
                __half2 p0 = __floats2half2_rn(a0.x, a0.y);
                __half2 p1 = __floats2half2_rn(a0.z, a0.w);
                __half2 p2 = __floats2half2_rn(a1.x, a1.y);
                __half2 p3 = __floats2half2_rn(a1.z, a1.w);
                val.x = reinterpret_cast<uint32_t&>(p0);
                val.y = reinterpret_cast<uint32_t&>(p1);
                val.z = reinterpret_cast<uint32_t&>(p2);
                val.w = reinterpret_cast<uint32_t&>(p3);
            } else {
                val = *(const uint4*)(root16 + (size_t)gr * 64 + (g - 8) * 8);
            }
        }
        *(uint4*)((char*)As + r * AROW_B + g * 16) = val;
    }

    // ---- stage Bt = W^T: Bt[nrow][k],  k<64 -> Wl[k][n], k>=64 -> Wr[k-64][n] ----
    for (int idx = tid; idx < 2048; idx += 128) {
        int k  = idx >> 4;      // 0..127
        int n4 = idx & 15;      // 4 n per unit
        const float* Wp = (k < 64) ? (Wl + (size_t)k * 64 + n4 * 4)
                                   : (Wr + (size_t)(k - 64) * 64 + n4 * 4);
        float4 w = *(const float4*)Wp;
        __half hv[4];
        hv[0] = __float2half_rn(w.x); hv[1] = __float2half_rn(w.y);
        hv[2] = __float2half_rn(w.z); hv[3] = __float2half_rn(w.w);
        #pragma unroll
        for (int j = 0; j < 4; j++)
            *(__half*)((char*)Bt + (n4 * 4 + j) * AROW_B + k * 2) = hv[j];
    }
    __syncthreads();

    const uint32_t a_base = smem_u32(As);
    const uint32_t b_base = smem_u32(Bt);

    float c[2][8][4];
    #pragma unroll
    for (int mf = 0; mf < 2; mf++)
        #pragma unroll
        for (int nf = 0; nf < 8; nf++)
            #pragma unroll
            for (int q = 0; q < 4; q++) c[mf][nf][q] = 0.f;

    #pragma unroll 1
    for (int ks = 0; ks < 8; ks++) {
        const int kb = ks * 16;
        // B fragments: 4x ldmatrix.x4 -> 8 n-frags x {b0,b1}
        uint32_t bf[8][2];
        #pragma unroll
        for (int q = 0; q < 4; q++) {
            int nrow = q * 16 + (lane & 7) + ((lane >> 4) & 1) * 8;
            int col  = kb + ((lane >> 3) & 1) * 8;
            uint32_t addr = b_base + nrow * AROW_B + col * 2;
            ldsm_x4(bf[2 * q][0], bf[2 * q][1], bf[2 * q + 1][0], bf[2 * q + 1][1], addr);
        }
        #pragma unroll
        for (int mf = 0; mf < 2; mf++) {
            int mrow = wid * 32 + mf * 16 + (lane & 7) + ((lane >> 3) & 1) * 8;
            int col  = kb + ((lane >> 4) & 1) * 8;
            uint32_t addr = a_base + mrow * AROW_B + col * 2;
            uint32_t a0, a1, a2, a3;
            ldsm_x4(a0, a1, a2, a3, addr);
            #pragma unroll
            for (int nf = 0; nf < 8; nf++)
                mma16816(c[mf][nf], a0, a1, a2, a3, bf[nf][0], bf[nf][1]);
        }
    }

    // ---- epilogue ----
    const float bov = do_head ? __ldg(bo) : 0.f;
    #pragma unroll
    for (int mf = 0; mf < 2; mf++) {
        int r0 = row0 + wid * 32 + mf * 16 + (lane >> 2);
        int r1 = r0 + 8;
        float h0 = 0.f, h1 = 0.f;
        #pragma unroll
        for (int nf = 0; nf < 8; nf++) {
            int c0 = nf * 8 + (lane & 3) * 2;
            float b0 = bias[c0], b1 = bias[c0 + 1];
            float f0 = c[mf][nf][0] + b0;
            float f1 = c[mf][nf][1] + b1;
            float f2 = c[mf][nf][2] + b0;
            float f3 = c[mf][nf][3] + b1;
            f0 = f0 > 0.f ? f0 : 0.01f * f0;
            f1 = f1 > 0.f ? f1 : 0.01f * f1;
            f2 = f2 > 0.f ? f2 : 0.01f * f2;
            f3 = f3 > 0.f ? f3 : 0.01f * f3;
            if (do_head) {
                float w0 = wos[c0], w1 = wos[c0 + 1];
                h0 += f0 * w0 + f1 * w1;
                h1 += f2 * w0 + f3 * w1;
            } else {
                if (r0 < n) {
                    __half2 p = __floats2half2_rn(f0, f1);
                    *(uint32_t*)(out16 + (size_t)r0 * 64 + c0) = reinterpret_cast<uint32_t&>(p);
                }
                if (r1 < n) {
                    __half2 p = __floats2half2_rn(f2, f3);
                    *(uint32_t*)(out16 + (size_t)r1 * 64 + c0) = reinterpret_cast<uint32_t&>(p);
                }
            }
        }
        if (do_head) {
            h0 += __shfl_xor_sync(0xffffffffu, h0, 1);
            h0 += __shfl_xor_sync(0xffffffffu, h0, 2);
            h1 += __shfl_xor_sync(0xffffffffu, h1, 1);
            h1 += __shfl_xor_sync(0xffffffffu, h1, 2);
            if ((lane & 3) == 0) {
                if (r0 < n) outv[r0] = h0 + bov;
                if (r1 < n) outv[r1] = h1 + bov;
            }
        }
    }
}

extern "C" void kernel_launch(void* const* d_in, const int* in_sizes, int n_in,
                              void* d_out, int out_size)
{
    const float* x   = (const float*)d_in[0];
    const int*   ei  = (const int*)d_in[1];
    const float* Wl1 = (const float*)d_in[2];
    const float* bl1 = (const float*)d_in[3];
    const float* Wr1 = (const float*)d_in[4];
    const float* Wl2 = (const float*)d_in[5];
    const float* bl2 = (const float*)d_in[6];
    const float* Wr2 = (const float*)d_in[7];
    const float* Wl3 = (const float*)d_in[8];
    const float* bl3 = (const float*)d_in[9];
    const float* Wr3 = (const float*)d_in[10];
    const float* Wo  = (const float*)d_in[11];
    const float* bo  = (const float*)d_in[12];
    float* out = (float*)d_out;

    const int n = in_sizes[0] / 64;
    const int e = in_sizes[1] / 2;

    __half *x16 = nullptr, *h16A = nullptr, *h16B = nullptr;
    cudaGetSymbolAddress((void**)&x16, g_x16);
    cudaGetSymbolAddress((void**)&h16A, g_h16A);
    cudaGetSymbolAddress((void**)&h16B, g_h16B);

    cudaFuncSetAttribute(k_transform_mma, cudaFuncAttributeMaxDynamicSharedMemorySize,
                         SM_TOT);

    const int n8  = n * 8;
    const int cb  = (n8 + 255) / 256;
    const int e4  = (e + 3) / 4;
    const int eb4 = (e4 + 255) / 256;
    const int nbs = (n + 1023) / 1024;
    const int ab  = (n * 8 + 255) / 256;      // aggregate: 8 lanes per node
    const int tb  = (n + 127) / 128;          // transform: 128 rows per block

    // conversion (+deg zero), then CSR build
    k_tofp16_zero<<<cb, 256>>>(x, x16, n8, n);
    k_count<<<eb4, 256>>>(ei, e);
    k_blocksum<<<nbs, 256>>>(n);
    k_offsets<<<nbs, 256>>>(n, e);
    k_place<<<eb4, 256>>>(ei, e);

    // layer 1: x16 -> h16A
    k_aggregate<<<ab, 256>>>(x16, n);
    k_transform_mma<<<tb, 128, SM_TOT>>>(x16, Wl1, bl1, Wr1, h16A,
                                         nullptr, nullptr, nullptr, n, 0);
    // layer 2: h16A -> h16B
    k_aggregate<<<ab, 256>>>(h16A, n);
    k_transform_mma<<<tb, 128, SM_TOT>>>(h16A, Wl2, bl2, Wr2, h16B,
                                         nullptr, nullptr, nullptr, n, 0);
    // layer 3 + head: h16B -> out
    k_aggregate<<<ab, 256>>>(h16B, n);
    k_transform_mma<<<tb, 128, SM_TOT>>>(h16B, Wl3, bl3, Wr3, nullptr,
                                         Wo, bo, out, n, 1);
}